// round 3
// baseline (speedup 1.0000x reference)
#include <cuda_runtime.h>

#define BB 2
#define CC 20
#define DD 256
#define WW 448
#define HWp 200704      // 448*448
#define FH 28
#define FW 28
#define FHW 784
#define KTOP 25

// ---- scratch (device globals; zeroed every launch by k_zero) ----
static __device__ float g_W  [BB*CC*FHW];   // bilinear weight field from pseudo-label mask
static __device__ float g_Wt [BB*CC*FHW];   // bilinear weight field from top-25 pixels
static __device__ int   g_cnt[BB*CC];       // pixel counts per (b,c)
static __device__ float g_fsm[BB*CC*DD];    // per-class features

__global__ void k_zero() {
    int i = blockIdx.x * 256 + threadIdx.x;
    if (i < BB*CC*FHW) { g_W[i] = 0.f; g_Wt[i] = 0.f; }
    if (i < BB*CC)     g_cnt[i] = 0;
}

__device__ __forceinline__ void upd(float v, int c, float& t1, float& t2, int& i1) {
    bool gt = v > t1;
    t2 = gt ? t1 : fmaxf(t2, v);
    i1 = gt ? c  : i1;
    t1 = gt ? v  : t1;
}

// ---- pseudo-label + bilinear-weight scatter. 4 pixels/thread via float4 ----
__global__ __launch_bounds__(256) void k_pseudo(
    const float* __restrict__ cam, const float* __restrict__ label,
    const float* __restrict__ hig, const float* __restrict__ low,
    const float* __restrict__ bg)
{
    __shared__ int s_np;
    __shared__ int s_list[CC];
    int t  = blockIdx.x * 256 + threadIdx.x;
    int gp = t * 4;                       // global pixel (b*HWp + p), block stays within one b
    int b  = gp / HWp;
    int p  = gp - b * HWp;
    if (threadIdx.x == 0) {
        int np = 0;
        for (int c = 0; c < CC; c++)
            if (__ldg(&label[b*CC + c]) > 0.5f) s_list[np++] = c;
        s_np = np;
    }
    __syncthreads();
    int np = s_np;
    const float* base = cam + (size_t)b * CC * HWp;

    float t1[4], t2[4]; int i1[4];
    #pragma unroll
    for (int e = 0; e < 4; e++) { t1[e] = -1e30f; t2[e] = -1e30f; i1[e] = 0; }

    for (int k = 0; k < np; k++) {
        int c = s_list[k];
        float4 v = __ldg((const float4*)(base + (size_t)c * HWp + p));
        upd(v.x, c, t1[0], t2[0], i1[0]);
        upd(v.y, c, t1[1], t2[1], i1[1]);
        upd(v.z, c, t1[2], t2[2], i1[2]);
        upd(v.w, c, t1[3], t2[3], i1[3]);
    }
    float Hh = __ldg(hig), Ll = __ldg(low), Gg = __ldg(bg);

    #pragma unroll
    for (int e = 0; e < 4; e++) {
        float a = t1[e], s = t2[e];
        if (np < CC) { a = fmaxf(a, 0.f); s = fmaxf(s, 0.f); }  // absent classes contribute zeros
        int ps = i1[e] + 1;
        if (a < Hh) ps = 255;
        if (a < Ll) ps = 0;
        if (a < Gg) ps = 0;
        if ((a - s < 0.3f) && (a > Hh)) ps = 255;
        if (ps >= 1 && ps <= CC) {
            int c = ps - 1;
            atomicAdd(&g_cnt[b*CC + c], 1);
            int pp = p + e;
            int y = pp / WW, x = pp - y * WW;
            float sy = ((float)y + 0.5f) * 0.0625f - 0.5f;   // exact (dyadic)
            float sx = ((float)x + 0.5f) * 0.0625f - 0.5f;
            float y0f = floorf(sy), x0f = floorf(sx);
            float fy = sy - y0f,   fx = sx - x0f;
            int y0 = (int)y0f, x0 = (int)x0f;
            int ya = min(max(y0, 0), FH-1),   yb = min(max(y0+1, 0), FH-1);
            int xa = min(max(x0, 0), FW-1),   xb = min(max(x0+1, 0), FW-1);
            float* Wp = &g_W[(b*CC + c) * FHW];
            atomicAdd(&Wp[ya*FW + xa], (1.f-fy)*(1.f-fx));
            atomicAdd(&Wp[ya*FW + xb], (1.f-fy)*fx);
            atomicAdd(&Wp[yb*FW + xa], fy*(1.f-fx));
            atomicAdd(&Wp[yb*FW + xb], fy*fx);
        }
    }
}

// ---- top-25 fallback: one block per (b,c); runs only when present && count==0 ----
__global__ __launch_bounds__(256) void k_topk(
    const float* __restrict__ cam, const float* __restrict__ label)
{
    int b = blockIdx.x / CC, c = blockIdx.x % CC;
    if (__ldg(&label[b*CC + c]) <= 0.5f) return;
    if (g_cnt[b*CC + c] != 0) return;

    int tid = threadIdx.x;
    const float4* cp = (const float4*)(cam + ((size_t)b*CC + c) * HWp);

    float vals[KTOP]; int idxs[KTOP];
    #pragma unroll
    for (int k = 0; k < KTOP; k++) { vals[k] = -1e30f; idxs[k] = -1; }
    float vmin = -1e30f;

    for (int j = tid; j < HWp/4; j += 256) {
        float4 v = __ldg(&cp[j]);
        int pbase = j * 4;
        float vv[4] = { v.x, v.y, v.z, v.w };
        #pragma unroll
        for (int e = 0; e < 4; e++) {
            float x = vv[e];
            if (x > vmin) {
                int k = 0;
                while (k < KTOP-1 && x > vals[k+1]) { vals[k] = vals[k+1]; idxs[k] = idxs[k+1]; k++; }
                vals[k] = x; idxs[k] = pbase + e;
                vmin = vals[0];
            }
        }
    }

    __shared__ float rv[256];
    __shared__ int   rpix[256];
    __shared__ int   s_top[KTOP];
    int ptr = KTOP - 1;
    for (int r = 0; r < KTOP; r++) {
        rv[tid]   = (ptr >= 0) ? vals[ptr] : -1e30f;
        rpix[tid] = (ptr >= 0) ? idxs[ptr] : -2;
        __syncthreads();
        for (int s = 128; s > 0; s >>= 1) {
            if (tid < s && rv[tid + s] > rv[tid]) { rv[tid] = rv[tid+s]; rpix[tid] = rpix[tid+s]; }
            __syncthreads();
        }
        int wp = rpix[0]; float wv = rv[0];
        if (tid == 0) s_top[r] = wp;
        __syncthreads();
        if (ptr >= 0 && idxs[ptr] == wp && vals[ptr] == wv) ptr--;
        __syncthreads();
    }

    if (tid == 0) {
        float* Wt = &g_Wt[(b*CC + c) * FHW];
        for (int r = 0; r < KTOP; r++) {
            int pp = s_top[r];
            int y = pp / WW, x = pp - y * WW;
            float sy = ((float)y + 0.5f) * 0.0625f - 0.5f;
            float sx = ((float)x + 0.5f) * 0.0625f - 0.5f;
            float y0f = floorf(sy), x0f = floorf(sx);
            float fy = sy - y0f,   fx = sx - x0f;
            int y0 = (int)y0f, x0 = (int)x0f;
            int ya = min(max(y0, 0), FH-1),   yb = min(max(y0+1, 0), FH-1);
            int xa = min(max(x0, 0), FW-1),   xb = min(max(x0+1, 0), FW-1);
            Wt[ya*FW + xa] += (1.f-fy)*(1.f-fx);
            Wt[ya*FW + xb] += (1.f-fy)*fx;
            Wt[yb*FW + xa] += fy*(1.f-fx);
            Wt[yb*FW + xb] += fy*fx;
        }
    }
}

// ---- fsm[b,c,d] = sum_q cw[q] * fmap[b,d,q] ----
__global__ __launch_bounds__(256) void k_fsm(
    const float* __restrict__ fmap, const float* __restrict__ label)
{
    int b = blockIdx.x / CC, c = blockIdx.x % CC;
    int tid = threadIdx.x;
    __shared__ float cw[FHW];
    bool present = __ldg(&label[b*CC + c]) > 0.5f;
    int  cnt = g_cnt[b*CC + c];
    float inv = (cnt > 0) ? (1.f / (float)cnt) : (1.f / 25.f);
    for (int q = tid; q < FHW; q += 256) {
        float w = 0.f;
        if (present) w = ((cnt > 0) ? g_W[(b*CC + c)*FHW + q] : g_Wt[(b*CC + c)*FHW + q]) * inv;
        cw[q] = w;
    }
    __syncthreads();
    const float4* fr  = (const float4*)(fmap + ((size_t)b * DD + tid) * FHW);
    const float4* cw4 = (const float4*)cw;
    float acc = 0.f;
    #pragma unroll 4
    for (int q = 0; q < FHW/4; q++) {
        float4 f = __ldg(&fr[q]);
        float4 w = cw4[q];
        acc = fmaf(f.x, w.x, acc); acc = fmaf(f.y, w.y, acc);
        acc = fmaf(f.z, w.z, acc); acc = fmaf(f.w, w.w, acc);
    }
    g_fsm[(b*CC + c)*DD + tid] = acc;
}

// ---- sequential loss (single block; B=2 steps with EMA memory bank) ----
__global__ __launch_bounds__(256) void k_loss(
    const float* __restrict__ label, const float* __restrict__ proj,
    const float* __restrict__ fc0, float* __restrict__ out)
{
    __shared__ float sfsm[CC][DD];
    __shared__ float sfc [CC][DD];
    __shared__ float nf[CC], ncv[CC];
    __shared__ float cosm[CC][CC];
    __shared__ float s_term[CC];
    __shared__ int   s_q[CC];
    __shared__ float s_rowsum[CC];
    __shared__ float s_acc[2];   // [0]=loss_ccf, [1]=loss_cls

    int tid = threadIdx.x, wid = tid >> 5, lane = tid & 31;
    for (int i = tid; i < CC*DD; i += 256) (&sfc[0][0])[i] = __ldg(&fc0[i]);
    if (tid == 0) { s_acc[0] = 0.f; s_acc[1] = 0.f; }
    __syncthreads();

    for (int b = 0; b < BB; b++) {
        for (int i = tid; i < CC*DD; i += 256) (&sfsm[0][0])[i] = g_fsm[b*CC*DD + i];
        __syncthreads();

        // row norms of fsm and fc
        for (int c = wid; c < CC; c += 8) {
            float a = 0.f, bb = 0.f;
            #pragma unroll
            for (int k = 0; k < DD/32; k++) {
                float x = sfsm[c][lane + 32*k]; a  = fmaf(x, x, a);
                float y = sfc [c][lane + 32*k]; bb = fmaf(y, y, bb);
            }
            #pragma unroll
            for (int o = 16; o > 0; o >>= 1) {
                a  += __shfl_down_sync(0xffffffffu, a,  o);
                bb += __shfl_down_sync(0xffffffffu, bb, o);
            }
            if (lane == 0) { nf[c] = sqrtf(a); ncv[c] = sqrtf(bb); }
        }
        __syncthreads();

        // cos matrix + logits/softmax BCE term, fsm row register-resident per warp
        for (int c = wid; c < CC; c += 8) {
            float rv[8];
            #pragma unroll
            for (int k = 0; k < 8; k++) rv[k] = sfsm[c][lane + 32*k];
            float invf = 1.f / fmaxf(nf[c], 1e-12f);

            for (int j = 0; j < CC; j++) {
                float pp = 0.f;
                #pragma unroll
                for (int k = 0; k < 8; k++) pp = fmaf(rv[k], sfc[j][lane + 32*k], pp);
                #pragma unroll
                for (int o = 16; o > 0; o >>= 1) pp += __shfl_down_sync(0xffffffffu, pp, o);
                if (lane == 0) {
                    float v = fabsf(pp * invf / fmaxf(ncv[j], 1e-12f));
                    v = fminf(fmaxf(v, 1e-5f), 1.f - 1e-5f);
                    cosm[c][j] = v;
                }
            }

            float lgv[CC];
            #pragma unroll
            for (int j = 0; j < CC; j++) {
                float pp = 0.f;
                #pragma unroll
                for (int k = 0; k < 8; k++)
                    pp = fmaf(rv[k], __ldg(&proj[j*DD + lane + 32*k]), pp);
                #pragma unroll
                for (int o = 16; o > 0; o >>= 1) pp += __shfl_down_sync(0xffffffffu, pp, o);
                lgv[j] = pp;
            }
            if (lane == 0) {
                float m = lgv[0];
                #pragma unroll
                for (int j = 1; j < CC; j++) m = fmaxf(m, lgv[j]);
                float s = 0.f; float pv[CC];
                #pragma unroll
                for (int j = 0; j < CC; j++) { pv[j] = expf(lgv[j] - m); s += pv[j]; }
                float inv = 1.f / s;
                float sum = 0.f;
                #pragma unroll
                for (int j = 0; j < CC; j++) {
                    float pr = pv[j] * inv;
                    float tt = (j == c) ? fmaxf(logf(pr), -100.f)
                                        : fmaxf(log1pf(-pr), -100.f);
                    sum += tt;
                }
                s_term[c] = -sum * (1.f / (float)CC);
            }
        }
        __syncthreads();

        // loss_ccf row sums, off-diag max, qualify
        if (tid < CC) {
            int c = tid;
            bool pres = __ldg(&label[b*CC + c]) > 0.5f;
            float rs = 0.f, om = -1e30f;
            for (int j = 0; j < CC; j++) {
                float v = cosm[c][j];
                if (j == c) rs += pres ? logf(v) : log1pf(-v);
                else        { rs += log1pf(-v); om = fmaxf(om, v); }
            }
            s_rowsum[c] = rs;
            s_q[c] = (pres && om < 0.6f) ? 1 : 0;
        }
        __syncthreads();

        if (tid == 0) {
            float tot = 0.f;
            for (int c = 0; c < CC; c++) tot += s_rowsum[c];
            s_acc[0] -= tot * (1.f / (float)(CC*CC));
            float ls = 0.f; int n = 0;
            for (int c = 0; c < CC; c++) if (s_q[c]) { ls += s_term[c]; n++; }
            s_acc[1] += ls;
            if (n > 0) s_acc[1] /= (float)n;      // divides the ACCUMULATED value, per reference
        }
        __syncthreads();

        // EMA memory-bank update for qualified rows
        for (int i = tid; i < CC*DD; i += 256) {
            int c = i >> 8;
            if (s_q[c]) (&sfc[0][0])[i] = 0.95f * (&sfc[0][0])[i] + 0.05f * (&sfsm[0][0])[i];
        }
        __syncthreads();
    }
    if (tid == 0) out[0] = s_acc[0] + s_acc[1];
}

extern "C" void kernel_launch(void* const* d_in, const int* in_sizes, int n_in,
                              void* d_out, int out_size)
{
    (void)in_sizes; (void)n_in; (void)out_size;
    const float* fmap  = (const float*)d_in[0];
    const float* cam   = (const float*)d_in[1];
    const float* label = (const float*)d_in[2];
    const float* proj  = (const float*)d_in[3];
    const float* fc0   = (const float*)d_in[4];
    const float* hig   = (const float*)d_in[5];
    const float* low   = (const float*)d_in[6];
    const float* bg    = (const float*)d_in[7];
    float* out = (float*)d_out;

    k_zero  <<<(BB*CC*FHW + 255) / 256, 256>>>();
    k_pseudo<<<(BB*HWp/4) / 256, 256>>>(cam, label, hig, low, bg);
    k_topk  <<<BB*CC, 256>>>(cam, label);
    k_fsm   <<<BB*CC, 256>>>(fmap, label);
    k_loss  <<<1, 256>>>(label, proj, fc0, out);
}

// round 4
// speedup vs baseline: 1.1835x; 1.1835x over previous
#include <cuda_runtime.h>

#define BB 2
#define CC 20
#define DD 256
#define WW 448
#define HWp 200704      // 448*448
#define FH 28
#define FW 28
#define FHW 784
#define KTOP 25
#define NCH 7           // q/pixel chunks
#define CHQ 112         // FHW / NCH
#define CHPX 28672      // HWp / NCH

// ---- scratch (device globals; zeroed every launch by k_zero) ----
static __device__ float g_W  [BB*CC*FHW];     // bilinear weight field from pseudo-label mask
static __device__ float g_Wt [BB*CC*FHW];     // bilinear weight field from top-25 pixels
static __device__ int   g_cnt[BB*CC];         // pixel counts per (b,c)
static __device__ float g_fsm[BB*CC*DD];      // per-class features (atomic-accumulated)
static __device__ float g_cv [BB*CC*NCH*KTOP]; // per-chunk top-k values (desc)
static __device__ int   g_ci [BB*CC*NCH*KTOP]; // per-chunk top-k pixel indices

__global__ void k_zero() {
    int i = blockIdx.x * 256 + threadIdx.x;
    if (i < BB*CC*FHW) { g_W[i] = 0.f; g_Wt[i] = 0.f; }
    if (i < BB*CC*DD)  g_fsm[i] = 0.f;
    if (i < BB*CC)     g_cnt[i] = 0;
}

__device__ __forceinline__ void upd(float v, int c, float& t1, float& t2, int& i1) {
    bool gt = v > t1;
    t2 = gt ? t1 : fmaxf(t2, v);
    i1 = gt ? c  : i1;
    t1 = gt ? v  : t1;
}

// ---- pseudo-label + bilinear-weight scatter, shared-mem aggregated ----
// grid = BB*196, 256 threads, 4 pixels/thread (1024 px = <=3 hi-res rows per block)
__global__ __launch_bounds__(256) void k_pseudo(
    const float* __restrict__ cam, const float* __restrict__ label,
    const float* __restrict__ hig, const float* __restrict__ low,
    const float* __restrict__ bg)
{
    __shared__ int   s_np;
    __shared__ int   s_list[CC];
    __shared__ float s_W[CC*3*30];   // [c][row 0..2][col 0..29] unclamped tile
    __shared__ int   s_cnt[CC];

    int tid = threadIdx.x;
    int b    = blockIdx.x / 196;
    int pblk = blockIdx.x % 196;
    int P0   = pblk * 1024;
    int p    = P0 + tid * 4;

    for (int i = tid; i < CC*90; i += 256) s_W[i] = 0.f;
    if (tid < CC) s_cnt[tid] = 0;
    if (tid == 0) {
        int np = 0;
        for (int c = 0; c < CC; c++)
            if (__ldg(&label[b*CC + c]) > 0.5f) s_list[np++] = c;
        s_np = np;
    }
    __syncthreads();

    int np = s_np;
    const float* base = cam + (size_t)b * CC * HWp;

    float t1[4], t2[4]; int i1[4];
    #pragma unroll
    for (int e = 0; e < 4; e++) { t1[e] = -1e30f; t2[e] = -1e30f; i1[e] = 0; }

    for (int k = 0; k < np; k++) {
        int c = s_list[k];
        float4 v = __ldg((const float4*)(base + (size_t)c * HWp + p));
        upd(v.x, c, t1[0], t2[0], i1[0]);
        upd(v.y, c, t1[1], t2[1], i1[1]);
        upd(v.z, c, t1[2], t2[2], i1[2]);
        upd(v.w, c, t1[3], t2[3], i1[3]);
    }
    float Hh = __ldg(hig), Ll = __ldg(low), Gg = __ldg(bg);

    int Y0 = P0 / WW;
    int r0 = (int)floorf(((float)Y0 + 0.5f) * 0.0625f - 0.5f);

    #pragma unroll
    for (int e = 0; e < 4; e++) {
        float a = t1[e], s = t2[e];
        if (np < CC) { a = fmaxf(a, 0.f); s = fmaxf(s, 0.f); }  // absent classes are zeros
        int ps = i1[e] + 1;
        if (a < Hh) ps = 255;
        if (a < Ll) ps = 0;
        if (a < Gg) ps = 0;
        if ((a - s < 0.3f) && (a > Hh)) ps = 255;
        if (ps >= 1 && ps <= CC) {
            int c = ps - 1;
            atomicAdd(&s_cnt[c], 1);
            int pp = p + e;
            int y = pp / WW, x = pp - y * WW;
            float sy = ((float)y + 0.5f) * 0.0625f - 0.5f;   // exact (dyadic)
            float sx = ((float)x + 0.5f) * 0.0625f - 0.5f;
            float y0f = floorf(sy), x0f = floorf(sx);
            float fy = sy - y0f,   fx = sx - x0f;
            int rr  = (int)y0f - r0;        // 0..1 (taps rr, rr+1 in [0,2])
            int c0  = (int)x0f + 1;         // 0..28
            float* tp = &s_W[c*90 + rr*30 + c0];
            atomicAdd(&tp[0],  (1.f-fy)*(1.f-fx));
            atomicAdd(&tp[1],  (1.f-fy)*fx);
            atomicAdd(&tp[30], fy*(1.f-fx));
            atomicAdd(&tp[31], fy*fx);
        }
    }
    __syncthreads();

    if (tid < CC && s_cnt[tid] > 0) atomicAdd(&g_cnt[b*CC + tid], s_cnt[tid]);
    for (int i = tid; i < CC*90; i += 256) {
        float v = s_W[i];
        if (v != 0.f) {
            int c = i / 90, rem = i - c*90;
            int rr = rem / 30, col = rem - rr*30;
            int gy = min(max(r0 + rr, 0), FH-1);
            int gx = min(max(col - 1, 0), FW-1);
            atomicAdd(&g_W[(b*CC + c)*FHW + gy*FW + gx], v);
        }
    }
}

// ---- top-25 chunk scan: grid BB*CC*NCH, 256 thr, 112 px/thread ----
__global__ __launch_bounds__(256) void k_topk_scan(
    const float* __restrict__ cam, const float* __restrict__ label)
{
    int blk = blockIdx.x;
    int ch  = blk % NCH;
    int bc  = blk / NCH;
    int b = bc / CC, c = bc % CC;
    if (__ldg(&label[b*CC + c]) <= 0.5f) return;
    if (g_cnt[bc] != 0) return;

    int tid = threadIdx.x, wid = tid >> 5, lane = tid & 31;
    const float4* cp = (const float4*)(cam + ((size_t)b*CC + c) * HWp) + ch * (CHPX/4);

    float vals[KTOP]; int idxs[KTOP];   // ascending: vals[24] = max
    #pragma unroll
    for (int k = 0; k < KTOP; k++) { vals[k] = -1e30f; idxs[k] = 0x7fffffff; }
    float vmin = -1e30f;

    for (int it = 0; it < 28; it++) {
        int j = tid + it * 256;
        float4 v = __ldg(&cp[j]);
        int pbase = ch * CHPX + j * 4;
        float vv[4] = { v.x, v.y, v.z, v.w };
        #pragma unroll
        for (int e = 0; e < 4; e++) {
            float x = vv[e];
            if (x > vmin) {
                int k = 0;
                while (k < KTOP-1 && x > vals[k+1]) { vals[k] = vals[k+1]; idxs[k] = idxs[k+1]; k++; }
                vals[k] = x; idxs[k] = pbase + e;
                vmin = vals[0];
            }
        }
    }

    // block top-25 via warp-shuffle argmax (2 syncs/round)
    __shared__ float s_wv[8];
    __shared__ int   s_wi[8];
    __shared__ int   s_bi;
    int ptr = KTOP - 1;
    for (int r = 0; r < KTOP; r++) {
        float v = (ptr >= 0) ? vals[ptr] : -1e30f;
        int   ii = (ptr >= 0) ? idxs[ptr] : 0x7fffffff;
        float mv = v; int mi = ii;
        #pragma unroll
        for (int off = 16; off > 0; off >>= 1) {
            float ov = __shfl_down_sync(0xffffffffu, mv, off);
            int   oi = __shfl_down_sync(0xffffffffu, mi, off);
            if (ov > mv || (ov == mv && oi < mi)) { mv = ov; mi = oi; }
        }
        if (lane == 0) { s_wv[wid] = mv; s_wi[wid] = mi; }
        __syncthreads();
        if (tid == 0) {
            float bv = s_wv[0]; int bi = s_wi[0];
            #pragma unroll
            for (int w = 1; w < 8; w++) {
                if (s_wv[w] > bv || (s_wv[w] == bv && s_wi[w] < bi)) { bv = s_wv[w]; bi = s_wi[w]; }
            }
            s_bi = bi;
            g_cv[blk*KTOP + r] = bv;
            g_ci[blk*KTOP + r] = bi;
        }
        __syncthreads();
        if (ptr >= 0 && idxs[ptr] == s_bi) ptr--;
    }
}

// ---- merge NCH chunk lists -> global top-25 -> Wt field. grid BB*CC, 32 thr ----
__global__ __launch_bounds__(32) void k_topk_merge(const float* __restrict__ label)
{
    int bc = blockIdx.x;
    int b = bc / CC, c = bc % CC;
    if (__ldg(&label[b*CC + c]) <= 0.5f) return;
    if (g_cnt[bc] != 0) return;

    int lane = threadIdx.x;
    __shared__ float s_wt[FHW];
    for (int i = lane; i < FHW; i += 32) s_wt[i] = 0.f;
    __syncwarp();

    int ptr = 0;
    float v = -1e30f; int ii = 0x7fffffff;
    if (lane < NCH) { v = g_cv[(bc*NCH + lane)*KTOP]; ii = g_ci[(bc*NCH + lane)*KTOP]; }

    for (int r = 0; r < KTOP; r++) {
        float bv = v; int bi = ii;
        #pragma unroll
        for (int off = 16; off > 0; off >>= 1) {
            float ov = __shfl_xor_sync(0xffffffffu, bv, off);
            int   oi = __shfl_xor_sync(0xffffffffu, bi, off);
            if (ov > bv || (ov == bv && oi < bi)) { bv = ov; bi = oi; }
        }
        if (lane == 0) {
            int pp = bi;
            int y = pp / WW, x = pp - y * WW;
            float sy = ((float)y + 0.5f) * 0.0625f - 0.5f;
            float sx = ((float)x + 0.5f) * 0.0625f - 0.5f;
            float y0f = floorf(sy), x0f = floorf(sx);
            float fy = sy - y0f,   fx = sx - x0f;
            int y0 = (int)y0f, x0 = (int)x0f;
            int ya = min(max(y0, 0), FH-1),   yb = min(max(y0+1, 0), FH-1);
            int xa = min(max(x0, 0), FW-1),   xb = min(max(x0+1, 0), FW-1);
            s_wt[ya*FW + xa] += (1.f-fy)*(1.f-fx);
            s_wt[ya*FW + xb] += (1.f-fy)*fx;
            s_wt[yb*FW + xa] += fy*(1.f-fx);
            s_wt[yb*FW + xb] += fy*fx;
        }
        if (lane < NCH && ii == bi) {
            ptr++;
            if (ptr < KTOP) { v = g_cv[(bc*NCH + lane)*KTOP + ptr]; ii = g_ci[(bc*NCH + lane)*KTOP + ptr]; }
            else            { v = -1e30f; ii = 0x7fffffff; }
        }
    }
    __syncwarp();
    for (int i = lane; i < FHW; i += 32) g_Wt[bc*FHW + i] = s_wt[i];
}

// ---- fsm[b,c,d] = sum_q cw[q]*fmap[b,d,q], chunked: grid BB*CC*NCH ----
__global__ __launch_bounds__(256) void k_fsm(
    const float* __restrict__ fmap, const float* __restrict__ label)
{
    int blk = blockIdx.x;
    int ch = blk % NCH;
    int bc = blk / NCH;
    int b = bc / CC;
    if (__ldg(&label[blk / NCH % (BB*CC) % CC + (bc/CC)*CC]) <= 0.5f) { /* never taken; real check below */ }
    if (__ldg(&label[bc]) <= 0.5f) return;   // label laid out as [B,CC] => flat index bc

    __shared__ float cw[CHQ];
    int cnt = g_cnt[bc];
    float inv = (cnt > 0) ? (1.f / (float)cnt) : (1.f / 25.f);
    const float* Wsrc = (cnt > 0) ? g_W : g_Wt;
    float my = 0.f;
    if (threadIdx.x < CHQ) {
        my = Wsrc[bc*FHW + ch*CHQ + threadIdx.x] * inv;
        cw[threadIdx.x] = my;
    }
    if (!__syncthreads_or(my != 0.f)) return;   // whole chunk weight-free

    int d = threadIdx.x;
    const float4* fr  = (const float4*)(fmap + ((size_t)b * DD + d) * FHW + ch * CHQ);
    const float4* cw4 = (const float4*)cw;
    float acc = 0.f;
    #pragma unroll
    for (int q = 0; q < CHQ/4; q++) {
        float4 f = __ldg(&fr[q]);
        float4 w = cw4[q];
        acc = fmaf(f.x, w.x, acc); acc = fmaf(f.y, w.y, acc);
        acc = fmaf(f.z, w.z, acc); acc = fmaf(f.w, w.w, acc);
    }
    atomicAdd(&g_fsm[bc*DD + d], acc);
}

// ---- sequential loss (single block; B=2 steps with EMA memory bank) ----
__global__ __launch_bounds__(256) void k_loss(
    const float* __restrict__ label, const float* __restrict__ proj,
    const float* __restrict__ fc0, float* __restrict__ out)
{
    __shared__ float sfsm[CC][DD];
    __shared__ float sfc [CC][DD];
    __shared__ float nf[CC], ncv[CC];
    __shared__ float cosm[CC][CC];
    __shared__ float s_term[CC];
    __shared__ int   s_q[CC];
    __shared__ float s_rowsum[CC];
    __shared__ float s_acc[2];   // [0]=loss_ccf, [1]=loss_cls

    int tid = threadIdx.x, wid = tid >> 5, lane = tid & 31;
    for (int i = tid; i < CC*DD; i += 256) (&sfc[0][0])[i] = __ldg(&fc0[i]);
    if (tid == 0) { s_acc[0] = 0.f; s_acc[1] = 0.f; }
    __syncthreads();

    for (int b = 0; b < BB; b++) {
        for (int i = tid; i < CC*DD; i += 256) (&sfsm[0][0])[i] = g_fsm[b*CC*DD + i];
        __syncthreads();

        for (int c = wid; c < CC; c += 8) {
            float a = 0.f, bb = 0.f;
            #pragma unroll
            for (int k = 0; k < DD/32; k++) {
                float x = sfsm[c][lane + 32*k]; a  = fmaf(x, x, a);
                float y = sfc [c][lane + 32*k]; bb = fmaf(y, y, bb);
            }
            #pragma unroll
            for (int o = 16; o > 0; o >>= 1) {
                a  += __shfl_down_sync(0xffffffffu, a,  o);
                bb += __shfl_down_sync(0xffffffffu, bb, o);
            }
            if (lane == 0) { nf[c] = sqrtf(a); ncv[c] = sqrtf(bb); }
        }
        __syncthreads();

        for (int c = wid; c < CC; c += 8) {
            float rv[8];
            #pragma unroll
            for (int k = 0; k < 8; k++) rv[k] = sfsm[c][lane + 32*k];
            float invf = 1.f / fmaxf(nf[c], 1e-12f);

            for (int j = 0; j < CC; j++) {
                float pp = 0.f;
                #pragma unroll
                for (int k = 0; k < 8; k++) pp = fmaf(rv[k], sfc[j][lane + 32*k], pp);
                #pragma unroll
                for (int o = 16; o > 0; o >>= 1) pp += __shfl_down_sync(0xffffffffu, pp, o);
                if (lane == 0) {
                    float v = fabsf(pp * invf / fmaxf(ncv[j], 1e-12f));
                    v = fminf(fmaxf(v, 1e-5f), 1.f - 1e-5f);
                    cosm[c][j] = v;
                }
            }

            float lgv[CC];
            #pragma unroll
            for (int j = 0; j < CC; j++) {
                float pp = 0.f;
                #pragma unroll
                for (int k = 0; k < 8; k++)
                    pp = fmaf(rv[k], __ldg(&proj[j*DD + lane + 32*k]), pp);
                #pragma unroll
                for (int o = 16; o > 0; o >>= 1) pp += __shfl_down_sync(0xffffffffu, pp, o);
                lgv[j] = pp;
            }
            if (lane == 0) {
                float m = lgv[0];
                #pragma unroll
                for (int j = 1; j < CC; j++) m = fmaxf(m, lgv[j]);
                float s = 0.f; float pv[CC];
                #pragma unroll
                for (int j = 0; j < CC; j++) { pv[j] = expf(lgv[j] - m); s += pv[j]; }
                float inv = 1.f / s;
                float sum = 0.f;
                #pragma unroll
                for (int j = 0; j < CC; j++) {
                    float pr = pv[j] * inv;
                    float tt = (j == c) ? fmaxf(logf(pr), -100.f)
                                        : fmaxf(log1pf(-pr), -100.f);
                    sum += tt;
                }
                s_term[c] = -sum * (1.f / (float)CC);
            }
        }
        __syncthreads();

        if (tid < CC) {
            int c = tid;
            bool pres = __ldg(&label[b*CC + c]) > 0.5f;
            float rs = 0.f, om = -1e30f;
            for (int j = 0; j < CC; j++) {
                float v = cosm[c][j];
                if (j == c) rs += pres ? logf(v) : log1pf(-v);
                else        { rs += log1pf(-v); om = fmaxf(om, v); }
            }
            s_rowsum[c] = rs;
            s_q[c] = (pres && om < 0.6f) ? 1 : 0;
        }
        __syncthreads();

        if (tid == 0) {
            float tot = 0.f;
            for (int c = 0; c < CC; c++) tot += s_rowsum[c];
            s_acc[0] -= tot * (1.f / (float)(CC*CC));
            float ls = 0.f; int n = 0;
            for (int c = 0; c < CC; c++) if (s_q[c]) { ls += s_term[c]; n++; }
            s_acc[1] += ls;
            if (n > 0) s_acc[1] /= (float)n;      // divides ACCUMULATED value, per reference
        }
        __syncthreads();

        for (int i = tid; i < CC*DD; i += 256) {
            int c = i >> 8;
            if (s_q[c]) (&sfc[0][0])[i] = 0.95f * (&sfc[0][0])[i] + 0.05f * (&sfsm[0][0])[i];
        }
        __syncthreads();
    }
    if (tid == 0) out[0] = s_acc[0] + s_acc[1];
}

extern "C" void kernel_launch(void* const* d_in, const int* in_sizes, int n_in,
                              void* d_out, int out_size)
{
    (void)in_sizes; (void)n_in; (void)out_size;
    const float* fmap  = (const float*)d_in[0];
    const float* cam   = (const float*)d_in[1];
    const float* label = (const float*)d_in[2];
    const float* proj  = (const float*)d_in[3];
    const float* fc0   = (const float*)d_in[4];
    const float* hig   = (const float*)d_in[5];
    const float* low   = (const float*)d_in[6];
    const float* bg    = (const float*)d_in[7];
    float* out = (float*)d_out;

    k_zero      <<<(BB*CC*FHW + 255) / 256, 256>>>();
    k_pseudo    <<<BB*196, 256>>>(cam, label, hig, low, bg);
    k_topk_scan <<<BB*CC*NCH, 256>>>(cam, label);
    k_topk_merge<<<BB*CC, 32>>>(label);
    k_fsm       <<<BB*CC*NCH, 256>>>(fmap, label);
    k_loss      <<<1, 256>>>(label, proj, fc0, out);
}

// round 6
// speedup vs baseline: 1.8930x; 1.5995x over previous
#include <cuda_runtime.h>

#define BB 2
#define CC 20
#define DD 256
#define WW 448
#define HWp 200704      // 448*448
#define FH 28
#define FW 28
#define FHW 784
#define KTOP 25
#define NCH 7           // chunks over lo-res q / hi-res pixels
#define CHQ 112         // FHW / NCH  (4 lo-res rows)
#define CHPX 28672      // HWp / NCH

// ---- scratch (device globals; zeroed every launch by k_zero) ----
static __device__ float g_W  [BB*CC*FHW];      // bilinear weight field from pseudo-label mask
static __device__ int   g_cnt[BB*CC];          // pixel counts per (b,c)
static __device__ float g_fsm[BB*CC*DD];       // per-class features (atomic-accumulated)
static __device__ float g_cv [BB*CC*NCH*KTOP]; // per-chunk top-k values (desc)
static __device__ int   g_ci [BB*CC*NCH*KTOP]; // per-chunk top-k pixel indices

__global__ void k_zero() {
    int i = blockIdx.x * 256 + threadIdx.x;
    if (i < BB*CC*FHW) g_W[i] = 0.f;
    if (i < BB*CC*DD)  g_fsm[i] = 0.f;
    if (i < BB*CC)     g_cnt[i] = 0;
}

// ---- pseudo-label + bilinear-weight scatter (fmax-only top-2 + rare rescan) ----
// grid = BB*196, 256 threads, 4 pixels/thread (1024 px <= 3 hi-res rows per block)
__global__ __launch_bounds__(256) void k_pseudo(
    const float* __restrict__ cam, const float* __restrict__ label,
    const float* __restrict__ hig, const float* __restrict__ low,
    const float* __restrict__ bg)
{
    __shared__ int   s_np;
    __shared__ int   s_list[CC];
    __shared__ float s_W[CC*3*30];   // [c][row 0..2][col 0..29] unclamped tile
    __shared__ int   s_cnt[CC];

    int tid = threadIdx.x;
    int b    = blockIdx.x / 196;
    int pblk = blockIdx.x % 196;
    int P0   = pblk * 1024;
    int p    = P0 + tid * 4;

    for (int i = tid; i < CC*90; i += 256) s_W[i] = 0.f;
    if (tid < CC) s_cnt[tid] = 0;
    if (tid < 32) {
        float lv = (tid < CC) ? __ldg(&label[b*CC + tid]) : 0.f;
        unsigned m = __ballot_sync(0xffffffffu, lv > 0.5f);
        if (tid < CC && lv > 0.5f) {
            int pos = __popc(m & ((1u << tid) - 1u));
            s_list[pos] = tid;
        }
        if (tid == 0) s_np = __popc(m);
    }
    __syncthreads();

    int np = s_np;
    const float* base = cam + (size_t)b * CC * HWp;

    float t1[4], t2[4];
    #pragma unroll
    for (int e = 0; e < 4; e++) { t1[e] = -1e30f; t2[e] = -1e30f; }

    for (int k = 0; k < np; k++) {
        int c = s_list[k];
        float4 v = __ldg((const float4*)(base + (size_t)c * HWp + p));
        float tm;
        tm = fminf(t1[0], v.x); t2[0] = fmaxf(t2[0], tm); t1[0] = fmaxf(t1[0], v.x);
        tm = fminf(t1[1], v.y); t2[1] = fmaxf(t2[1], tm); t1[1] = fmaxf(t1[1], v.y);
        tm = fminf(t1[2], v.z); t2[2] = fmaxf(t2[2], tm); t1[2] = fmaxf(t1[2], v.z);
        tm = fminf(t1[3], v.w); t2[3] = fmaxf(t2[3], tm); t1[3] = fmaxf(t1[3], v.w);
    }
    float Hh = __ldg(hig), Ll = __ldg(low), Gg = __ldg(bg);

    int Y0 = P0 / WW;
    int r0 = (int)floorf(((float)Y0 + 0.5f) * 0.0625f - 0.5f);

    #pragma unroll
    for (int e = 0; e < 4; e++) {
        float a = t1[e], s = t2[e];
        if (np < CC) { a = fmaxf(a, 0.f); s = fmaxf(s, 0.f); }  // absent classes are zeros
        // labeled <=> survives the full threshold chain with ps in [1..CC]
        bool lab = !(a < Hh) && !(a < Ll) && !(a < Gg) && !((a - s < 0.3f) && (a > Hh));
        lab = lab && (np > 0);
        if (lab) {
            int c = s_list[0];
            if (np > 1) {
                int pp0 = p + e;
                for (int k = 0; k < np; k++) {
                    int cc2 = s_list[k];
                    if (__ldg(&base[(size_t)cc2 * HWp + pp0]) == a) { c = cc2; break; }
                }
            }
            atomicAdd(&s_cnt[c], 1);
            int pp = p + e;
            int y = pp / WW, x = pp - y * WW;
            float sy = ((float)y + 0.5f) * 0.0625f - 0.5f;   // exact (dyadic)
            float sx = ((float)x + 0.5f) * 0.0625f - 0.5f;
            float y0f = floorf(sy), x0f = floorf(sx);
            float fy = sy - y0f,   fx = sx - x0f;
            int rr  = (int)y0f - r0;        // 0..1 (taps rr, rr+1 in [0,2])
            int c0  = (int)x0f + 1;         // 0..28
            float* tp = &s_W[c*90 + rr*30 + c0];
            atomicAdd(&tp[0],  (1.f-fy)*(1.f-fx));
            atomicAdd(&tp[1],  (1.f-fy)*fx);
            atomicAdd(&tp[30], fy*(1.f-fx));
            atomicAdd(&tp[31], fy*fx);
        }
    }
    __syncthreads();

    if (tid < CC && s_cnt[tid] > 0) atomicAdd(&g_cnt[b*CC + tid], s_cnt[tid]);
    for (int i = tid; i < CC*90; i += 256) {
        float v = s_W[i];
        if (v != 0.f) {
            int c = i / 90, rem = i - c*90;
            int rr = rem / 30, col = rem - rr*30;
            int gy = min(max(r0 + rr, 0), FH-1);
            int gx = min(max(col - 1, 0), FW-1);
            atomicAdd(&g_W[(b*CC + c)*FHW + gy*FW + gx], v);
        }
    }
}

// ---- top-25 chunk scan: grid BB*CC*NCH, 256 thr, 112 px/thread ----
__global__ __launch_bounds__(256) void k_topk_scan(
    const float* __restrict__ cam, const float* __restrict__ label)
{
    int blk = blockIdx.x;
    int ch  = blk % NCH;
    int bc  = blk / NCH;
    int b = bc / CC, c = bc % CC;
    if (__ldg(&label[b*CC + c]) <= 0.5f) return;
    if (g_cnt[bc] != 0) return;

    int tid = threadIdx.x, wid = tid >> 5, lane = tid & 31;
    const float4* cp = (const float4*)(cam + ((size_t)b*CC + c) * HWp) + ch * (CHPX/4);

    float vals[KTOP]; int idxs[KTOP];   // ascending: vals[24] = max
    #pragma unroll
    for (int k = 0; k < KTOP; k++) { vals[k] = -1e30f; idxs[k] = 0x7fffffff; }
    float vmin = -1e30f;

    for (int it = 0; it < 28; it++) {
        int j = tid + it * 256;
        float4 v = __ldg(&cp[j]);
        int pbase = ch * CHPX + j * 4;
        float vv[4] = { v.x, v.y, v.z, v.w };
        #pragma unroll
        for (int e = 0; e < 4; e++) {
            float x = vv[e];
            if (x > vmin) {
                int k = 0;
                while (k < KTOP-1 && x > vals[k+1]) { vals[k] = vals[k+1]; idxs[k] = idxs[k+1]; k++; }
                vals[k] = x; idxs[k] = pbase + e;
                vmin = vals[0];
            }
        }
    }

    __shared__ float s_wv[8];
    __shared__ int   s_wi[8];
    __shared__ int   s_bi;
    int ptr = KTOP - 1;
    for (int r = 0; r < KTOP; r++) {
        float v  = (ptr >= 0) ? vals[ptr] : -1e30f;
        int   ii = (ptr >= 0) ? idxs[ptr] : 0x7fffffff;
        float mv = v; int mi = ii;
        #pragma unroll
        for (int off = 16; off > 0; off >>= 1) {
            float ov = __shfl_down_sync(0xffffffffu, mv, off);
            int   oi = __shfl_down_sync(0xffffffffu, mi, off);
            if (ov > mv || (ov == mv && oi < mi)) { mv = ov; mi = oi; }
        }
        if (lane == 0) { s_wv[wid] = mv; s_wi[wid] = mi; }
        __syncthreads();
        if (tid == 0) {
            float bv = s_wv[0]; int bi = s_wi[0];
            #pragma unroll
            for (int w = 1; w < 8; w++) {
                if (s_wv[w] > bv || (s_wv[w] == bv && s_wi[w] < bi)) { bv = s_wv[w]; bi = s_wi[w]; }
            }
            s_bi = bi;
            g_cv[blk*KTOP + r] = bv;
            g_ci[blk*KTOP + r] = bi;
        }
        __syncthreads();
        if (ptr >= 0 && idxs[ptr] == s_bi) ptr--;
    }
}

// ---- fsm[b,c,d] += sum_q cw[q]*fmap[b,d,q]; cnt==0 path merges top-25 inline ----
__global__ __launch_bounds__(256) void k_fsm(
    const float* __restrict__ fmap, const float* __restrict__ label)
{
    int blk = blockIdx.x;
    int ch = blk % NCH;
    int bc = blk / NCH;
    int b  = bc / CC;
    if (__ldg(&label[bc]) <= 0.5f) return;   // label is [B,CC] flat => index bc

    __shared__ float cw[CHQ];
    __shared__ float s_cv[NCH*KTOP];
    __shared__ int   s_ci[NCH*KTOP];
    __shared__ int   s_has;

    int tid = threadIdx.x;
    int cnt = g_cnt[bc];

    if (cnt > 0) {
        float my = 0.f;
        if (tid < CHQ) {
            my = g_W[bc*FHW + ch*CHQ + tid] * (1.f / (float)cnt);
            cw[tid] = my;
        }
        if (!__syncthreads_or(my != 0.f)) return;   // whole chunk weight-free
    } else {
        // coalesced preload of all 7 chunk candidate lists
        if (tid < NCH*KTOP) { s_cv[tid] = g_cv[bc*NCH*KTOP + tid]; s_ci[tid] = g_ci[bc*NCH*KTOP + tid]; }
        if (tid < CHQ) cw[tid] = 0.f;
        if (tid == 0)  s_has = 0;
        __syncthreads();

        if (tid < 32) {
            int lane = tid;
            int ptr = 0;
            float v = -1e30f; int ii = 0x7fffffff;
            if (lane < NCH) { v = s_cv[lane*KTOP]; ii = s_ci[lane*KTOP]; }
            int row0 = ch * 4;                       // chunk covers lo-res rows row0..row0+3
            int has = 0;
            for (int r = 0; r < KTOP; r++) {
                float bv = v; int bi = ii;
                #pragma unroll
                for (int off = 4; off > 0; off >>= 1) {   // lanes 0..7 reduce (7 real + sentinel)
                    float ov = __shfl_xor_sync(0xffffffffu, bv, off);
                    int   oi = __shfl_xor_sync(0xffffffffu, bi, off);
                    if (ov > bv || (ov == bv && oi < bi)) { bv = ov; bi = oi; }
                }
                if (lane == 0) {
                    int pp = bi;
                    int y = pp / WW, x = pp - y * WW;
                    float sy = ((float)y + 0.5f) * 0.0625f - 0.5f;
                    float sx = ((float)x + 0.5f) * 0.0625f - 0.5f;
                    float y0f = floorf(sy), x0f = floorf(sx);
                    float fy = sy - y0f,   fx = sx - x0f;
                    int y0 = (int)y0f, x0 = (int)x0f;
                    int ya = min(max(y0, 0), FH-1),   yb = min(max(y0+1, 0), FH-1);
                    int xa = min(max(x0, 0), FW-1),   xb = min(max(x0+1, 0), FW-1);
                    const float inv25 = 0.04f;
                    if (ya >= row0 && ya < row0+4) {
                        cw[(ya-row0)*FW + xa] += (1.f-fy)*(1.f-fx) * inv25;
                        cw[(ya-row0)*FW + xb] += (1.f-fy)*fx       * inv25;
                        has = 1;
                    }
                    if (yb >= row0 && yb < row0+4) {
                        cw[(yb-row0)*FW + xa] += fy*(1.f-fx) * inv25;
                        cw[(yb-row0)*FW + xb] += fy*fx       * inv25;
                        has = 1;
                    }
                }
                if (lane < NCH && ii == bi) {         // pop from winning chunk list
                    ptr++;
                    if (ptr < KTOP) { v = s_cv[lane*KTOP + ptr]; ii = s_ci[lane*KTOP + ptr]; }
                    else            { v = -1e30f; ii = 0x7fffffff; }
                }
            }
            if (lane == 0 && has) s_has = 1;
        }
        __syncthreads();
        if (!s_has) return;
    }

    int d = tid;
    const float4* fr  = (const float4*)(fmap + ((size_t)b * DD + d) * FHW + ch * CHQ);
    const float4* cw4 = (const float4*)cw;
    float acc = 0.f;
    #pragma unroll
    for (int q = 0; q < CHQ/4; q++) {
        float4 f = __ldg(&fr[q]);
        float4 w = cw4[q];
        acc = fmaf(f.x, w.x, acc); acc = fmaf(f.y, w.y, acc);
        acc = fmaf(f.z, w.z, acc); acc = fmaf(f.w, w.w, acc);
    }
    atomicAdd(&g_fsm[bc*DD + d], acc);
}

// ---- sequential loss (single block, 20 warps; B=2 steps with EMA memory bank) ----
__global__ __launch_bounds__(640) void k_loss(
    const float* __restrict__ label, const float* __restrict__ proj,
    const float* __restrict__ fc0, float* __restrict__ out)
{
    __shared__ float sfsm[CC][DD];
    __shared__ float sfc [CC][DD];
    __shared__ float nf[CC], ncv[CC];
    __shared__ float cosm[CC][CC];
    __shared__ float s_term[CC];
    __shared__ int   s_q[CC];
    __shared__ float s_rowsum[CC];
    __shared__ float s_acc[2];   // [0]=loss_ccf, [1]=loss_cls

    int tid = threadIdx.x, wid = tid >> 5, lane = tid & 31;
    for (int i = tid; i < CC*DD; i += 640) (&sfc[0][0])[i] = __ldg(&fc0[i]);
    if (tid == 0) { s_acc[0] = 0.f; s_acc[1] = 0.f; }
    __syncthreads();

    for (int b = 0; b < BB; b++) {
        for (int i = tid; i < CC*DD; i += 640) (&sfsm[0][0])[i] = g_fsm[b*CC*DD + i];
        __syncthreads();

        {   // row norms (one class per warp)
            int c = wid;
            float a = 0.f, bb = 0.f;
            #pragma unroll
            for (int k = 0; k < DD/32; k++) {
                float x = sfsm[c][lane + 32*k]; a  = fmaf(x, x, a);
                float y = sfc [c][lane + 32*k]; bb = fmaf(y, y, bb);
            }
            #pragma unroll
            for (int o = 16; o > 0; o >>= 1) {
                a  += __shfl_down_sync(0xffffffffu, a,  o);
                bb += __shfl_down_sync(0xffffffffu, bb, o);
            }
            if (lane == 0) { nf[c] = sqrtf(a); ncv[c] = sqrtf(bb); }
        }
        __syncthreads();

        {   // cos matrix + softmax-BCE term (one class per warp)
            int c = wid;
            float rv[8];
            #pragma unroll
            for (int k = 0; k < 8; k++) rv[k] = sfsm[c][lane + 32*k];
            float invf = 1.f / fmaxf(nf[c], 1e-12f);

            for (int j = 0; j < CC; j++) {
                float pp = 0.f;
                #pragma unroll
                for (int k = 0; k < 8; k++) pp = fmaf(rv[k], sfc[j][lane + 32*k], pp);
                #pragma unroll
                for (int o = 16; o > 0; o >>= 1) pp += __shfl_down_sync(0xffffffffu, pp, o);
                if (lane == 0) {
                    float v = fabsf(pp * invf / fmaxf(ncv[j], 1e-12f));
                    v = fminf(fmaxf(v, 1e-5f), 1.f - 1e-5f);
                    cosm[c][j] = v;
                }
            }

            float lgv[CC];
            #pragma unroll
            for (int j = 0; j < CC; j++) {
                float pp = 0.f;
                #pragma unroll
                for (int k = 0; k < 8; k++)
                    pp = fmaf(rv[k], __ldg(&proj[j*DD + lane + 32*k]), pp);
                #pragma unroll
                for (int o = 16; o > 0; o >>= 1) pp += __shfl_down_sync(0xffffffffu, pp, o);
                lgv[j] = pp;
            }
            if (lane == 0) {
                float m = lgv[0];
                #pragma unroll
                for (int j = 1; j < CC; j++) m = fmaxf(m, lgv[j]);
                float s = 0.f; float pv[CC];
                #pragma unroll
                for (int j = 0; j < CC; j++) { pv[j] = expf(lgv[j] - m); s += pv[j]; }
                float inv = 1.f / s;
                float sum = 0.f;
                #pragma unroll
                for (int j = 0; j < CC; j++) {
                    float pr = pv[j] * inv;
                    float tt = (j == c) ? fmaxf(logf(pr), -100.f)
                                        : fmaxf(log1pf(-pr), -100.f);
                    sum += tt;
                }
                s_term[c] = -sum * (1.f / (float)CC);
            }
        }
        __syncthreads();

        if (tid < CC) {
            int c = tid;
            bool pres = __ldg(&label[b*CC + c]) > 0.5f;
            float rs = 0.f, om = -1e30f;
            for (int j = 0; j < CC; j++) {
                float v = cosm[c][j];
                if (j == c) rs += pres ? logf(v) : log1pf(-v);
                else        { rs += log1pf(-v); om = fmaxf(om, v); }
            }
            s_rowsum[c] = rs;
            s_q[c] = (pres && om < 0.6f) ? 1 : 0;
        }
        __syncthreads();

        if (tid == 0) {
            float tot = 0.f;
            for (int c = 0; c < CC; c++) tot += s_rowsum[c];
            s_acc[0] -= tot * (1.f / (float)(CC*CC));
            float ls = 0.f; int n = 0;
            for (int c = 0; c < CC; c++) if (s_q[c]) { ls += s_term[c]; n++; }
            s_acc[1] += ls;
            if (n > 0) s_acc[1] /= (float)n;      // divides ACCUMULATED value, per reference
        }
        __syncthreads();

        for (int i = tid; i < CC*DD; i += 640) {
            int c = i >> 8;
            if (s_q[c]) (&sfc[0][0])[i] = 0.95f * (&sfc[0][0])[i] + 0.05f * (&sfsm[0][0])[i];
        }
        __syncthreads();
    }
    if (tid == 0) out[0] = s_acc[0] + s_acc[1];
}

extern "C" void kernel_launch(void* const* d_in, const int* in_sizes, int n_in,
                              void* d_out, int out_size)
{
    (void)in_sizes; (void)n_in; (void)out_size;
    const float* fmap  = (const float*)d_in[0];
    const float* cam   = (const float*)d_in[1];
    const float* label = (const float*)d_in[2];
    const float* proj  = (const float*)d_in[3];
    const float* fc0   = (const float*)d_in[4];
    const float* hig   = (const float*)d_in[5];
    const float* low   = (const float*)d_in[6];
    const float* bg    = (const float*)d_in[7];
    float* out = (float*)d_out;

    k_zero      <<<(BB*CC*FHW + 255) / 256, 256>>>();
    k_pseudo    <<<BB*196, 256>>>(cam, label, hig, low, bg);
    k_topk_scan <<<BB*CC*NCH, 256>>>(cam, label);
    k_fsm       <<<BB*CC*NCH, 256>>>(fmap, label);
    k_loss      <<<1, 640>>>(label, proj, fc0, out);
}

// round 7
// speedup vs baseline: 2.1015x; 1.1102x over previous
#include <cuda_runtime.h>

#define BB 2
#define CC 20
#define DD 256
#define WW 448
#define HWp 200704      // 448*448
#define FH 28
#define FW 28
#define FHW 784
#define KTOP 25
#define NCH 7           // chunks over lo-res q / hi-res pixels
#define CHQ 112         // FHW / NCH  (4 lo-res rows)
#define CHPX 28672      // HWp / NCH

// ---- scratch (device globals) ----
static __device__ float g_W   [BB*CC*FHW];      // bilinear weight field (pseudo-label mask); zeroed
static __device__ float g_Wt  [BB*CC*FHW];      // top-25 weight field; fully overwritten before read
static __device__ int   g_cnt [BB*CC];          // pixel counts per (b,c); zeroed
static __device__ int   g_done[BB*CC];          // chunk fan-in counters; zeroed
static __device__ float g_fsm [BB*CC*DD];       // per-class features (atomic-accumulated); zeroed
static __device__ float g_cv  [BB*CC*NCH*KTOP]; // per-chunk top-k values (desc); overwritten before read
static __device__ int   g_ci  [BB*CC*NCH*KTOP]; // per-chunk top-k pixel indices

__global__ void k_zero() {
    int i = blockIdx.x * 256 + threadIdx.x;
    if (i < BB*CC*FHW) g_W[i] = 0.f;
    if (i < BB*CC*DD)  g_fsm[i] = 0.f;
    if (i < BB*CC)     { g_cnt[i] = 0; g_done[i] = 0; }
}

// ---- pseudo-label + bilinear-weight scatter (fmax-only top-2 + rare rescan) ----
// grid = BB*196, 256 threads, 4 pixels/thread (1024 px <= 3 hi-res rows per block)
__global__ __launch_bounds__(256) void k_pseudo(
    const float* __restrict__ cam, const float* __restrict__ label,
    const float* __restrict__ hig, const float* __restrict__ low,
    const float* __restrict__ bg)
{
    __shared__ int   s_np;
    __shared__ int   s_list[CC];
    __shared__ float s_W[CC*3*30];   // [c][row 0..2][col 0..29] unclamped tile
    __shared__ int   s_cnt[CC];

    int tid = threadIdx.x;
    int b    = blockIdx.x / 196;
    int pblk = blockIdx.x % 196;
    int P0   = pblk * 1024;
    int p    = P0 + tid * 4;

    for (int i = tid; i < CC*90; i += 256) s_W[i] = 0.f;
    if (tid < CC) s_cnt[tid] = 0;
    if (tid < 32) {
        float lv = (tid < CC) ? __ldg(&label[b*CC + tid]) : 0.f;
        unsigned m = __ballot_sync(0xffffffffu, lv > 0.5f);
        if (tid < CC && lv > 0.5f) {
            int pos = __popc(m & ((1u << tid) - 1u));
            s_list[pos] = tid;
        }
        if (tid == 0) s_np = __popc(m);
    }
    __syncthreads();

    int np = s_np;
    const float* base = cam + (size_t)b * CC * HWp;

    float t1[4], t2[4];
    #pragma unroll
    for (int e = 0; e < 4; e++) { t1[e] = -1e30f; t2[e] = -1e30f; }

    for (int k = 0; k < np; k++) {
        int c = s_list[k];
        float4 v = __ldg((const float4*)(base + (size_t)c * HWp + p));
        float tm;
        tm = fminf(t1[0], v.x); t2[0] = fmaxf(t2[0], tm); t1[0] = fmaxf(t1[0], v.x);
        tm = fminf(t1[1], v.y); t2[1] = fmaxf(t2[1], tm); t1[1] = fmaxf(t1[1], v.y);
        tm = fminf(t1[2], v.z); t2[2] = fmaxf(t2[2], tm); t1[2] = fmaxf(t1[2], v.z);
        tm = fminf(t1[3], v.w); t2[3] = fmaxf(t2[3], tm); t1[3] = fmaxf(t1[3], v.w);
    }
    float Hh = __ldg(hig), Ll = __ldg(low), Gg = __ldg(bg);

    int Y0 = P0 / WW;
    int r0 = (int)floorf(((float)Y0 + 0.5f) * 0.0625f - 0.5f);

    #pragma unroll
    for (int e = 0; e < 4; e++) {
        float a = t1[e], s = t2[e];
        if (np < CC) { a = fmaxf(a, 0.f); s = fmaxf(s, 0.f); }  // absent classes are zeros
        bool lab = !(a < Hh) && !(a < Ll) && !(a < Gg) && !((a - s < 0.3f) && (a > Hh));
        lab = lab && (np > 0);
        if (lab) {
            int c = s_list[0];
            if (np > 1) {
                int pp0 = p + e;
                for (int k = 0; k < np; k++) {
                    int cc2 = s_list[k];
                    if (__ldg(&base[(size_t)cc2 * HWp + pp0]) == a) { c = cc2; break; }
                }
            }
            atomicAdd(&s_cnt[c], 1);
            int pp = p + e;
            int y = pp / WW, x = pp - y * WW;
            float sy = ((float)y + 0.5f) * 0.0625f - 0.5f;   // exact (dyadic)
            float sx = ((float)x + 0.5f) * 0.0625f - 0.5f;
            float y0f = floorf(sy), x0f = floorf(sx);
            float fy = sy - y0f,   fx = sx - x0f;
            int rr  = (int)y0f - r0;        // 0..1 (taps rr, rr+1 in [0,2])
            int c0  = (int)x0f + 1;         // 0..28
            float* tp = &s_W[c*90 + rr*30 + c0];
            atomicAdd(&tp[0],  (1.f-fy)*(1.f-fx));
            atomicAdd(&tp[1],  (1.f-fy)*fx);
            atomicAdd(&tp[30], fy*(1.f-fx));
            atomicAdd(&tp[31], fy*fx);
        }
    }
    __syncthreads();

    if (tid < CC && s_cnt[tid] > 0) atomicAdd(&g_cnt[b*CC + tid], s_cnt[tid]);
    for (int i = tid; i < CC*90; i += 256) {
        float v = s_W[i];
        if (v != 0.f) {
            int c = i / 90, rem = i - c*90;
            int rr = rem / 30, col = rem - rr*30;
            int gy = min(max(r0 + rr, 0), FH-1);
            int gx = min(max(col - 1, 0), FW-1);
            atomicAdd(&g_W[(b*CC + c)*FHW + gy*FW + gx], v);
        }
    }
}

// ---- top-25 chunk scan + fan-in merge: grid BB*CC*NCH, 256 thr ----
__global__ __launch_bounds__(256) void k_topk_scan(
    const float* __restrict__ cam, const float* __restrict__ label)
{
    int blk = blockIdx.x;
    int ch  = blk % NCH;
    int bc  = blk / NCH;
    int b = bc / CC, c = bc % CC;
    if (__ldg(&label[b*CC + c]) <= 0.5f) return;
    if (g_cnt[bc] != 0) return;

    int tid = threadIdx.x, wid = tid >> 5, lane = tid & 31;
    const float4* cp = (const float4*)(cam + ((size_t)b*CC + c) * HWp) + ch * (CHPX/4);

    float vals[KTOP]; int idxs[KTOP];   // ascending: vals[24] = max
    #pragma unroll
    for (int k = 0; k < KTOP; k++) { vals[k] = -1e30f; idxs[k] = 0x7fffffff; }
    float vmin = -1e30f;

    for (int it = 0; it < 28; it++) {
        int j = tid + it * 256;
        float4 v = __ldg(&cp[j]);
        int pbase = ch * CHPX + j * 4;
        float vv[4] = { v.x, v.y, v.z, v.w };
        #pragma unroll
        for (int e = 0; e < 4; e++) {
            float x = vv[e];
            if (x > vmin) {
                int k = 0;
                while (k < KTOP-1 && x > vals[k+1]) { vals[k] = vals[k+1]; idxs[k] = idxs[k+1]; k++; }
                vals[k] = x; idxs[k] = pbase + e;
                vmin = vals[0];
            }
        }
    }

    __shared__ float s_wv[8];
    __shared__ int   s_wi[8];
    __shared__ int   s_bi;
    int ptr = KTOP - 1;
    for (int r = 0; r < KTOP; r++) {
        float v  = (ptr >= 0) ? vals[ptr] : -1e30f;
        int   ii = (ptr >= 0) ? idxs[ptr] : 0x7fffffff;
        float mv = v; int mi = ii;
        #pragma unroll
        for (int off = 16; off > 0; off >>= 1) {
            float ov = __shfl_down_sync(0xffffffffu, mv, off);
            int   oi = __shfl_down_sync(0xffffffffu, mi, off);
            if (ov > mv || (ov == mv && oi < mi)) { mv = ov; mi = oi; }
        }
        if (lane == 0) { s_wv[wid] = mv; s_wi[wid] = mi; }
        __syncthreads();
        if (tid == 0) {
            float bv = s_wv[0]; int bi = s_wi[0];
            #pragma unroll
            for (int w = 1; w < 8; w++) {
                if (s_wv[w] > bv || (s_wv[w] == bv && s_wi[w] < bi)) { bv = s_wv[w]; bi = s_wi[w]; }
            }
            s_bi = bi;
            g_cv[blk*KTOP + r] = bv;
            g_ci[blk*KTOP + r] = bi;
        }
        __syncthreads();
        if (ptr >= 0 && idxs[ptr] == s_bi) ptr--;
    }

    // ---- fan-in: last chunk block merges the 7 lists and writes g_Wt[bc] ----
    __threadfence();
    __shared__ int s_last;
    if (tid == 0) s_last = (atomicAdd(&g_done[bc], 1) == NCH-1) ? 1 : 0;
    __syncthreads();
    if (!s_last) return;
    __threadfence();

    __shared__ float m_cv[NCH*KTOP];
    __shared__ int   m_ci[NCH*KTOP];
    __shared__ float s_wt[FHW];
    if (tid < NCH*KTOP) {
        m_cv[tid] = __ldcg(&g_cv[bc*NCH*KTOP + tid]);
        m_ci[tid] = __ldcg(&g_ci[bc*NCH*KTOP + tid]);
    }
    for (int i = tid; i < FHW; i += 256) s_wt[i] = 0.f;
    __syncthreads();

    if (tid < 32) {
        int ptr2 = 0;
        float v = -1e30f; int ii = 0x7fffffff;
        if (lane < NCH) { v = m_cv[lane*KTOP]; ii = m_ci[lane*KTOP]; }
        for (int r = 0; r < KTOP; r++) {
            float bv = v; int bi = ii;
            #pragma unroll
            for (int off = 4; off > 0; off >>= 1) {
                float ov = __shfl_xor_sync(0xffffffffu, bv, off);
                int   oi = __shfl_xor_sync(0xffffffffu, bi, off);
                if (ov > bv || (ov == bv && oi < bi)) { bv = ov; bi = oi; }
            }
            if (lane == 0) {
                int pp = bi;
                int y = pp / WW, x = pp - y * WW;
                float sy = ((float)y + 0.5f) * 0.0625f - 0.5f;
                float sx = ((float)x + 0.5f) * 0.0625f - 0.5f;
                float y0f = floorf(sy), x0f = floorf(sx);
                float fy = sy - y0f,   fx = sx - x0f;
                int y0 = (int)y0f, x0 = (int)x0f;
                int ya = min(max(y0, 0), FH-1),   yb = min(max(y0+1, 0), FH-1);
                int xa = min(max(x0, 0), FW-1),   xb = min(max(x0+1, 0), FW-1);
                s_wt[ya*FW + xa] += (1.f-fy)*(1.f-fx);
                s_wt[ya*FW + xb] += (1.f-fy)*fx;
                s_wt[yb*FW + xa] += fy*(1.f-fx);
                s_wt[yb*FW + xb] += fy*fx;
            }
            if (lane < NCH && ii == bi) {
                ptr2++;
                if (ptr2 < KTOP) { v = m_cv[lane*KTOP + ptr2]; ii = m_ci[lane*KTOP + ptr2]; }
                else             { v = -1e30f; ii = 0x7fffffff; }
            }
        }
    }
    __syncthreads();
    for (int i = tid; i < FHW; i += 256) g_Wt[bc*FHW + i] = s_wt[i];
}

// ---- fused fsm: grid = BB*NCH*2 (d-half), 128 threads; fmap chunk in registers,
//      all present-class weights in shared -> 20x fmap reuse ----
__global__ __launch_bounds__(128) void k_fsm(
    const float* __restrict__ fmap, const float* __restrict__ label)
{
    __shared__ int   s_np, s_nact;
    __shared__ int   s_list[CC];
    __shared__ int   s_act[CC];
    __shared__ int   s_nz[CC];
    __shared__ float4 s_cw[CC*28];   // [class][28 float4] = chunk weights * inv

    int tid  = threadIdx.x;
    int half = blockIdx.x & 1;
    int ch   = (blockIdx.x >> 1) % NCH;
    int b    = blockIdx.x / (2*NCH);
    int wid  = tid >> 5, lane = tid & 31;

    if (tid < 32) {
        float lv = (tid < CC) ? __ldg(&label[b*CC + tid]) : 0.f;
        unsigned m = __ballot_sync(0xffffffffu, lv > 0.5f);
        if (tid < CC && lv > 0.5f) s_list[__popc(m & ((1u << tid) - 1u))] = tid;
        if (tid == 0) s_np = __popc(m);
    }
    __syncthreads();
    int np = s_np;

    for (int k = wid; k < np; k += 4) {
        int c  = s_list[k];
        int bc = b*CC + c;
        int cnt = g_cnt[bc];
        float inv = (cnt > 0) ? (1.f / (float)cnt) : 0.04f;
        const float* src = (cnt > 0) ? (g_W + bc*FHW + ch*CHQ) : (g_Wt + bc*FHW + ch*CHQ);
        float4 v = make_float4(0.f, 0.f, 0.f, 0.f);
        if (lane < 28) {
            v = ((const float4*)src)[lane];
            v.x *= inv; v.y *= inv; v.z *= inv; v.w *= inv;
            s_cw[k*28 + lane] = v;
        }
        int nz = __any_sync(0xffffffffu,
                 (lane < 28) && (v.x != 0.f || v.y != 0.f || v.z != 0.f || v.w != 0.f));
        if (lane == 0) s_nz[k] = nz;
    }
    __syncthreads();

    if (tid < 32) {
        bool a = (tid < np) && s_nz[tid];
        unsigned m = __ballot_sync(0xffffffffu, a);
        if (a) s_act[__popc(m & ((1u << tid) - 1u))] = tid;
        if (tid == 0) s_nact = __popc(m);
    }
    __syncthreads();
    int nact = s_nact;
    if (nact == 0) return;

    int d = half*128 + tid;
    const float4* fr = (const float4*)(fmap + ((size_t)(b*DD + d)) * FHW + ch*CHQ);
    float4 f[28];
    #pragma unroll
    for (int i = 0; i < 28; i++) f[i] = __ldg(&fr[i]);

    for (int a = 0; a < nact; a++) {
        int k = s_act[a];
        int c = s_list[k];
        float a0 = 0.f, a1 = 0.f, a2 = 0.f, a3 = 0.f;
        #pragma unroll
        for (int i = 0; i < 28; i++) {
            float4 w = s_cw[k*28 + i];
            a0 = fmaf(f[i].x, w.x, a0);
            a1 = fmaf(f[i].y, w.y, a1);
            a2 = fmaf(f[i].z, w.z, a2);
            a3 = fmaf(f[i].w, w.w, a3);
        }
        atomicAdd(&g_fsm[(b*CC + c)*DD + d], (a0 + a1) + (a2 + a3));
    }
}

// ---- sequential loss (single block, 20 warps; B=2 steps with EMA memory bank) ----
__global__ __launch_bounds__(640) void k_loss(
    const float* __restrict__ label, const float* __restrict__ proj,
    const float* __restrict__ fc0, float* __restrict__ out)
{
    __shared__ float sfsm[CC][DD];
    __shared__ float sfc [CC][DD];
    __shared__ float nf[CC], ncv[CC];
    __shared__ float cosm[CC][CC];
    __shared__ float s_term[CC];
    __shared__ int   s_q[CC];
    __shared__ float s_rowsum[CC];
    __shared__ float s_acc[2];   // [0]=loss_ccf, [1]=loss_cls

    int tid = threadIdx.x, wid = tid >> 5, lane = tid & 31;
    for (int i = tid; i < CC*DD; i += 640) (&sfc[0][0])[i] = __ldg(&fc0[i]);
    if (tid == 0) { s_acc[0] = 0.f; s_acc[1] = 0.f; }
    __syncthreads();

    for (int b = 0; b < BB; b++) {
        for (int i = tid; i < CC*DD; i += 640) (&sfsm[0][0])[i] = g_fsm[b*CC*DD + i];
        __syncthreads();

        {   // row norms (one class per warp)
            int c = wid;
            float a = 0.f, bb = 0.f;
            #pragma unroll
            for (int k = 0; k < DD/32; k++) {
                float x = sfsm[c][lane + 32*k]; a  = fmaf(x, x, a);
                float y = sfc [c][lane + 32*k]; bb = fmaf(y, y, bb);
            }
            #pragma unroll
            for (int o = 16; o > 0; o >>= 1) {
                a  += __shfl_xor_sync(0xffffffffu, a,  o);
                bb += __shfl_xor_sync(0xffffffffu, bb, o);
            }
            if (lane == 0) { nf[c] = sqrtf(a); ncv[c] = sqrtf(bb); }
        }
        __syncthreads();

        {   // cos matrix + softmax-BCE term (one class per warp)
            int c = wid;
            float rv[8];
            #pragma unroll
            for (int k = 0; k < 8; k++) rv[k] = sfsm[c][lane + 32*k];
            float invf = 1.f / fmaxf(nf[c], 1e-12f);

            float mycos = 0.f;
            #pragma unroll
            for (int j = 0; j < CC; j++) {
                float pp = 0.f;
                #pragma unroll
                for (int k = 0; k < 8; k++) pp = fmaf(rv[k], sfc[j][lane + 32*k], pp);
                #pragma unroll
                for (int o = 16; o > 0; o >>= 1) pp += __shfl_xor_sync(0xffffffffu, pp, o);
                float v = fabsf(pp * invf / fmaxf(ncv[j], 1e-12f));
                v = fminf(fmaxf(v, 1e-5f), 1.f - 1e-5f);
                if (lane == j) mycos = v;
            }
            if (lane < CC) cosm[c][lane] = mycos;

            float mylg = 0.f;
            #pragma unroll
            for (int j = 0; j < CC; j++) {
                float pp = 0.f;
                #pragma unroll
                for (int k = 0; k < 8; k++)
                    pp = fmaf(rv[k], __ldg(&proj[j*DD + lane + 32*k]), pp);
                #pragma unroll
                for (int o = 16; o > 0; o >>= 1) pp += __shfl_xor_sync(0xffffffffu, pp, o);
                if (lane == j) mylg = pp;
            }
            // parallel softmax + BCE over lanes 0..19
            float x = (lane < CC) ? mylg : -3.4e38f;
            float m = x;
            #pragma unroll
            for (int o = 16; o > 0; o >>= 1) m = fmaxf(m, __shfl_xor_sync(0xffffffffu, m, o));
            float e = (lane < CC) ? expf(x - m) : 0.f;
            float ssum = e;
            #pragma unroll
            for (int o = 16; o > 0; o >>= 1) ssum += __shfl_xor_sync(0xffffffffu, ssum, o);
            float t = 0.f;
            if (lane < CC) {
                float pr = e / ssum;
                t = (lane == c) ? fmaxf(logf(pr), -100.f) : fmaxf(log1pf(-pr), -100.f);
            }
            #pragma unroll
            for (int o = 16; o > 0; o >>= 1) t += __shfl_xor_sync(0xffffffffu, t, o);
            if (lane == 0) s_term[c] = -t * (1.f / (float)CC);
        }
        __syncthreads();

        if (tid < CC) {
            int c = tid;
            bool pres = __ldg(&label[b*CC + c]) > 0.5f;
            float rs = 0.f, om = -1e30f;
            for (int j = 0; j < CC; j++) {
                float v = cosm[c][j];
                if (j == c) rs += pres ? logf(v) : log1pf(-v);
                else        { rs += log1pf(-v); om = fmaxf(om, v); }
            }
            s_rowsum[c] = rs;
            s_q[c] = (pres && om < 0.6f) ? 1 : 0;
        }
        __syncthreads();

        if (tid == 0) {
            float tot = 0.f;
            for (int c = 0; c < CC; c++) tot += s_rowsum[c];
            s_acc[0] -= tot * (1.f / (float)(CC*CC));
            float ls = 0.f; int n = 0;
            for (int c = 0; c < CC; c++) if (s_q[c]) { ls += s_term[c]; n++; }
            s_acc[1] += ls;
            if (n > 0) s_acc[1] /= (float)n;      // divides ACCUMULATED value, per reference
        }
        __syncthreads();

        for (int i = tid; i < CC*DD; i += 640) {
            int c = i >> 8;
            if (s_q[c]) (&sfc[0][0])[i] = 0.95f * (&sfc[0][0])[i] + 0.05f * (&sfsm[0][0])[i];
        }
        __syncthreads();
    }
    if (tid == 0) out[0] = s_acc[0] + s_acc[1];
}

extern "C" void kernel_launch(void* const* d_in, const int* in_sizes, int n_in,
                              void* d_out, int out_size)
{
    (void)in_sizes; (void)n_in; (void)out_size;
    const float* fmap  = (const float*)d_in[0];
    const float* cam   = (const float*)d_in[1];
    const float* label = (const float*)d_in[2];
    const float* proj  = (const float*)d_in[3];
    const float* fc0   = (const float*)d_in[4];
    const float* hig   = (const float*)d_in[5];
    const float* low   = (const float*)d_in[6];
    const float* bg    = (const float*)d_in[7];
    float* out = (float*)d_out;

    k_zero      <<<(BB*CC*FHW + 255) / 256, 256>>>();
    k_pseudo    <<<BB*196, 256>>>(cam, label, hig, low, bg);
    k_topk_scan <<<BB*CC*NCH, 256>>>(cam, label);
    k_fsm       <<<BB*NCH*2, 128>>>(fmap, label);
    k_loss      <<<1, 640>>>(label, proj, fc0, out);
}